// round 1
// baseline (speedup 1.0000x reference)
#include <cuda_runtime.h>
#include <cstdint>

#define NROI 6144
#define NCLS 20
#define KSEL 615            // ceil(0.1 * 6144)
#define NSORT 8192
#define IOU_TH 0.25f

// ---- scratch (device globals; no allocations allowed) ----
__device__ unsigned char g_keep[NCLS * NROI];
__device__ int   g_cls[NROI];     // 0 = no gt label, else c+1
__device__ float g_w[NROI];       // gt weight (init -1 semantics)
__device__ int   g_list[NROI];    // compacted gt indices
__device__ int   g_cnt;           // number of gt indices

// ============================================================
// Kernel 1: one block per class.
//  - build composite sort keys (~float_bits(prob) << 32 | idx):
//    ascending u64 order == (prob descending, index ascending),
//    exactly matching jnp.argsort(-prob) stable semantics.
//  - bitonic sort 8192 entries in shared memory
//  - greedy NMS over top-615 (gathers from iou_map)
//  - scatter keep mask
// ============================================================
__global__ void class_nms_kernel(const float* __restrict__ pc,
                                 const float* __restrict__ pd,
                                 const float* __restrict__ iou) {
    extern __shared__ unsigned long long s[];          // NSORT u64 = 64KB
    __shared__ volatile unsigned char alive[KSEL];
    __shared__ unsigned char keep[KSEL];

    const int c   = blockIdx.x;
    const int tid = threadIdx.x;
    const int nt  = blockDim.x;

    if (c == 0 && tid == 0) g_cnt = 0;                 // reset for combine kernel

    // zero this class's keep-mask slice
    for (int i = tid; i < NROI; i += nt) g_keep[c * NROI + i] = 0;

    // load composite keys (prob = predict_cls[:,c+1] * predict_det[:,c+1])
    for (int i = tid; i < NSORT; i += nt) {
        if (i < NROI) {
            float p = pc[i * (NCLS + 1) + c + 1] * pd[i * (NCLS + 1) + c + 1];
            unsigned int fb = __float_as_uint(p);      // p >= 0: bit order == value order
            s[i] = ((unsigned long long)(~fb) << 32) | (unsigned int)i;
        } else {
            s[i] = 0xFFFFFFFFFFFFFFFFull;              // padding sorts last
        }
    }
    __syncthreads();

    // bitonic sort, ascending in composite
    for (unsigned int k = 2; k <= NSORT; k <<= 1) {
        for (unsigned int j = k >> 1; j > 0; j >>= 1) {
            for (unsigned int i = tid; i < NSORT; i += nt) {
                unsigned int ixj = i ^ j;
                if (ixj > i) {
                    unsigned long long a = s[i], b = s[ixj];
                    bool asc = ((i & k) == 0);
                    if ((a > b) == asc) { s[i] = b; s[ixj] = a; }
                }
            }
            __syncthreads();
        }
    }

    // greedy NMS over sorted top-KSEL candidates
    for (int i = tid; i < KSEL; i += nt) { alive[i] = 1; keep[i] = 0; }
    __syncthreads();

    for (int i = 0; i < KSEL; ++i) {
        if (alive[i]) {                                 // uniform read (same smem addr)
            int oi = (unsigned int)s[i];
            if (tid == 0) keep[i] = 1;
            int j = i + 1 + tid;                        // nt=1024 >= KSEL: <=1 per thread
            if (j < KSEL) {
                if (alive[j]) {
                    int oj = (unsigned int)s[j];
                    float v = iou[(size_t)oi * NROI + oj];
                    if (v >= IOU_TH) alive[j] = 0;
                }
            }
            __syncthreads();
        }
    }

    // scatter keep mask back to ROI space
    for (int i = tid; i < KSEL; i += nt)
        if (keep[i]) g_keep[c * NROI + (unsigned int)s[i]] = 1;
}

// ============================================================
// Kernel 2: per-ROI sequential class loop (exactly replicates the
// reference's sequential gt_weights update) + gt-index compaction.
// ============================================================
__global__ void combine_kernel(const float* __restrict__ pc,
                               const float* __restrict__ pd,
                               const int* __restrict__ labels) {
    int i = blockIdx.x * blockDim.x + threadIdx.x;
    if (i >= NROI) return;
    float w = -1.0f;
    int cls = 0;
    #pragma unroll
    for (int c = 0; c < NCLS; ++c) {
        if (labels[c] > 0 && g_keep[c * NROI + i]) {
            float p = pc[i * (NCLS + 1) + c + 1] * pd[i * (NCLS + 1) + c + 1];
            if (p > w) { w = p; cls = c + 1; }
        }
    }
    g_cls[i] = cls;
    g_w[i]   = w;
    if (cls > 0) {
        int pos = atomicAdd(&g_cnt, 1);
        g_list[pos] = i;
    }
}

// ============================================================
// Kernel 3: masked max/argmax over gt columns.
// iou_map is exactly symmetric (0.5*(u+u^T), diag=1), so we read
// rows iou[gt*N + i] => coalesced across i.
// Tie-break: smallest column index among equal maxima (jnp.argmax).
// ============================================================
__global__ void final_kernel(const float* __restrict__ iou,
                             float* __restrict__ out) {
    int i = blockIdx.x * blockDim.x + threadIdx.x;
    if (i >= NROI) return;
    int G = g_cnt;
    float maxv = -1.0f;
    int   maxj = 0;
    for (int g = 0; g < G; ++g) {
        int j = __ldg(&g_list[g]);
        float v = iou[(size_t)j * NROI + i];
        if (v > maxv || (v == maxv && j < maxj)) { maxv = v; maxj = j; }
    }
    int   cls = g_cls[maxj];
    float lw  = g_w[maxj];
    bool ignore = (maxv == 0.0f);
    bool bg     = (maxv < IOU_TH) && !ignore;
    int lab = ignore ? -1 : (bg ? 0 : cls);
    #pragma unroll
    for (int k = 0; k <= NCLS; ++k)
        out[(size_t)i * (NCLS + 1) + k] = (k == lab) ? 1.0f : 0.0f;
    out[(size_t)NROI * (NCLS + 1) + i]        = maxv;             // pseudo_iou_label
    out[(size_t)NROI * (NCLS + 1) + NROI + i] = ignore ? 0.0f : lw; // loss_weights
}

extern "C" void kernel_launch(void* const* d_in, const int* in_sizes, int n_in,
                              void* d_out, int out_size) {
    const float* pc     = (const float*)d_in[0];  // predict_cls (N, C+1)
    const float* pd     = (const float*)d_in[1];  // predict_det (N, C+1)
    // d_in[2] = rois (unused by the reference output)
    const int*   labels = (const int*)d_in[3];    // (C,)
    const float* iou    = (const float*)d_in[4];  // (N, N)
    float* out = (float*)d_out;

    cudaFuncSetAttribute(class_nms_kernel,
                         cudaFuncAttributeMaxDynamicSharedMemorySize,
                         NSORT * (int)sizeof(unsigned long long));

    class_nms_kernel<<<NCLS, 1024, NSORT * sizeof(unsigned long long)>>>(pc, pd, iou);
    combine_kernel<<<(NROI + 255) / 256, 256>>>(pc, pd, labels);
    final_kernel<<<(NROI + 255) / 256, 256>>>(iou, out);
}

// round 2
// speedup vs baseline: 2.7290x; 2.7290x over previous
#include <cuda_runtime.h>
#include <cstdint>

#define NROI 6144
#define NCLS 20
#define KSEL 615            // ceil(0.1 * 6144)
#define CSORT 1024          // candidate sort size (pow2 >= max ties+KSEL slack)
#define AW 20               // ceil(KSEL/32) alive-bitmask words
#define IOU_TH 0.25f

// ---- scratch (device globals; no allocations allowed) ----
__device__ float g_predsT[NCLS * NROI];   // transposed preds[c][i]
__device__ unsigned char g_keep[NCLS * NROI];
__device__ int   g_cls[NROI];
__device__ float g_w[NROI];
__device__ int   g_list[NROI];
__device__ int   g_cnt;

// ============================================================
// Kernel 0: coalesced transpose of preds = pc[:,1:]*pd[:,1:]
// block = 128 threads handles 128 rows (21 cols each)
// ============================================================
__global__ void preds_kernel(const float* __restrict__ pc,
                             const float* __restrict__ pd) {
    __shared__ float sp[128 * 21];
    const int i0 = blockIdx.x * 128;
    for (int idx = threadIdx.x; idx < 128 * 21; idx += blockDim.x)
        sp[idx] = pc[i0 * 21 + idx] * pd[i0 * 21 + idx];
    __syncthreads();
    #pragma unroll
    for (int c = 0; c < NCLS; ++c)
        for (int i = threadIdx.x; i < 128; i += blockDim.x)
            g_predsT[c * NROI + i0 + i] = sp[i * 21 + c + 1];  // stride 21: conflict-free
}

// ============================================================
// Kernel 1: one block per class (20 blocks, 1024 threads)
//   radix-select 615th key -> compact candidates -> sort 1024
//   -> bitmask greedy NMS -> scatter keep
// ============================================================
__global__ void __launch_bounds__(1024, 1)
class_nms_kernel(const float* __restrict__ iou) {
    __shared__ unsigned int skey[NROI];                 // 24KB
    __shared__ unsigned long long cand[CSORT];          // 8KB
    __shared__ unsigned int sh_hist[256];
    __shared__ unsigned int sh_prefix, sh_k;
    __shared__ int sh_nc, sh_next;
    __shared__ unsigned int am[AW];

    const int c   = blockIdx.x;
    const int tid = threadIdx.x;
    const int nt  = blockDim.x;

    if (c == 0 && tid == 0) g_cnt = 0;                  // reset for combine

    // zero this class's keep slice
    for (int i = tid; i < NROI; i += nt) g_keep[c * NROI + i] = 0;

    // build inverted float keys: ascending key == descending prob
    for (int i = tid; i < NROI; i += nt)
        skey[i] = ~__float_as_uint(g_predsT[c * NROI + i]);

    if (tid == 0) { sh_prefix = 0; sh_k = KSEL; }
    __syncthreads();

    // ---- 4-pass MSB radix select for the KSEL-th smallest key ----
    for (int shift = 24; shift >= 0; shift -= 8) {
        for (int b = tid; b < 256; b += nt) sh_hist[b] = 0;
        __syncthreads();
        const unsigned int prefix = sh_prefix;
        const unsigned int pmask  = (shift == 24) ? 0u : (0xFFFFFFFFu << (shift + 8));
        for (int i = tid; i < NROI; i += nt) {
            unsigned int key = skey[i];
            if ((key & pmask) == prefix)
                atomicAdd(&sh_hist[(key >> shift) & 0xFF], 1u);
        }
        __syncthreads();
        if (tid == 0) {
            unsigned int cum = 0, k = sh_k;
            for (int b = 0; b < 256; ++b) {
                unsigned int h = sh_hist[b];
                if (cum + h >= k) { sh_prefix = prefix | ((unsigned int)b << shift); sh_k = k - cum; break; }
                cum += h;
            }
        }
        __syncthreads();
    }
    const unsigned int thr = sh_prefix;   // exact key of 615th-smallest

    // ---- compact candidates (key <= thr), composite = (key<<32)|idx ----
    if (tid == 0) sh_nc = 0;
    __syncthreads();
    for (int i = tid; i < NROI; i += nt) {
        unsigned int key = skey[i];
        if (key <= thr) {
            int pos = atomicAdd(&sh_nc, 1);
            if (pos < CSORT)
                cand[pos] = ((unsigned long long)key << 32) | (unsigned int)i;
        }
    }
    __syncthreads();
    const int nc = sh_nc;
    for (int i = tid; i < CSORT; i += nt)
        if (i >= nc) cand[i] = 0xFFFFFFFFFFFFFFFFull;
    __syncthreads();

    // ---- bitonic sort 1024 u64 ascending (prob desc, idx asc) ----
    for (unsigned int k = 2; k <= CSORT; k <<= 1) {
        for (unsigned int j = k >> 1; j > 0; j >>= 1) {
            unsigned int i = tid, ixj = i ^ j;
            if (ixj > i) {
                unsigned long long a = cand[i], b = cand[ixj];
                bool asc = ((i & k) == 0);
                if ((a > b) == asc) { cand[i] = b; cand[ixj] = a; }
            }
            __syncthreads();
        }
    }

    // ---- greedy NMS on cand[0..KSEL-1] with alive bitmask + skip scan ----
    for (int w = tid; w < AW; w += nt) am[w] = 0xFFFFFFFFu;
    if (tid == 0) {
        am[AW - 1] = (1u << (KSEL - 32 * (AW - 1))) - 1;  // tail: 7 bits
        sh_next = 0;
    }
    __syncthreads();

    while (true) {
        const int i = sh_next;
        if (i >= KSEL) break;
        const int oi = (unsigned int)cand[i];
        if (tid == 0) g_keep[c * NROI + oi] = 1;
        const int j = i + 1 + tid;                       // nt >= KSEL: one j per thread
        if (j < KSEL) {
            const int oj = (unsigned int)cand[j];
            float v = iou[(size_t)oi * NROI + oj];
            if (v >= IOU_TH) atomicAnd(&am[j >> 5], ~(1u << (j & 31)));
        }
        __syncthreads();
        if (tid == 0) {
            int nx = KSEL;
            int start = i + 1;
            int w = start >> 5;
            unsigned int m = (w < AW) ? (am[w] & (0xFFFFFFFFu << (start & 31))) : 0u;
            while (true) {
                if (m) { nx = (w << 5) + __ffs(m) - 1; break; }
                if (++w >= AW) break;
                m = am[w];
            }
            sh_next = nx;
        }
        __syncthreads();
    }
}

// ============================================================
// Kernel 2: per-ROI sequential class resolution + gt compaction
// ============================================================
__global__ void combine_kernel(const int* __restrict__ labels) {
    int i = blockIdx.x * blockDim.x + threadIdx.x;
    if (i >= NROI) return;
    float w = -1.0f;
    int cls = 0;
    #pragma unroll
    for (int c = 0; c < NCLS; ++c) {
        if (labels[c] > 0 && g_keep[c * NROI + i]) {
            float p = g_predsT[c * NROI + i];           // coalesced
            if (p > w) { w = p; cls = c + 1; }
        }
    }
    g_cls[i] = cls;
    g_w[i]   = w;
    if (cls > 0) {
        int pos = atomicAdd(&g_cnt, 1);
        g_list[pos] = i;
    }
}

// ============================================================
// Kernel 3: masked max/argmax over gt columns (symmetric iou =>
// read rows => coalesced). Tie-break: smallest column index.
// ============================================================
__global__ void final_kernel(const float* __restrict__ iou,
                             float* __restrict__ out) {
    int i = blockIdx.x * blockDim.x + threadIdx.x;
    if (i >= NROI) return;
    int G = g_cnt;
    float maxv = -1.0f;
    int   maxj = 0;
    for (int g = 0; g < G; ++g) {
        int j = __ldg(&g_list[g]);
        float v = iou[(size_t)j * NROI + i];
        if (v > maxv || (v == maxv && j < maxj)) { maxv = v; maxj = j; }
    }
    int   cls = g_cls[maxj];
    float lw  = g_w[maxj];
    bool ignore = (maxv == 0.0f);
    bool bg     = (maxv < IOU_TH) && !ignore;
    int lab = ignore ? -1 : (bg ? 0 : cls);
    #pragma unroll
    for (int k = 0; k <= NCLS; ++k)
        out[(size_t)i * (NCLS + 1) + k] = (k == lab) ? 1.0f : 0.0f;
    out[(size_t)NROI * (NCLS + 1) + i]        = maxv;
    out[(size_t)NROI * (NCLS + 1) + NROI + i] = ignore ? 0.0f : lw;
}

extern "C" void kernel_launch(void* const* d_in, const int* in_sizes, int n_in,
                              void* d_out, int out_size) {
    const float* pc     = (const float*)d_in[0];
    const float* pd     = (const float*)d_in[1];
    // d_in[2] = rois (unused)
    const int*   labels = (const int*)d_in[3];
    const float* iou    = (const float*)d_in[4];
    float* out = (float*)d_out;

    preds_kernel<<<NROI / 128, 128>>>(pc, pd);
    class_nms_kernel<<<NCLS, 1024>>>(iou);
    combine_kernel<<<(NROI + 255) / 256, 256>>>(labels);
    final_kernel<<<(NROI + 255) / 256, 256>>>(iou, out);
}

// round 3
// speedup vs baseline: 3.9284x; 1.4395x over previous
#include <cuda_runtime.h>
#include <cstdint>

#define NROI 6144
#define NCLS 20
#define KSEL 615            // ceil(0.1 * 6144)
#define CSORT 1024          // candidate sort size
#define AW 20               // ceil(KSEL/32) alive-bitmask words
#define IOU_TH 0.25f
#define FB 64               // final_kernel block size

// ---- scratch (device globals; no allocations allowed) ----
__device__ float g_predsT[NCLS * NROI];
__device__ unsigned char g_keep[NCLS * NROI];
__device__ int   g_cls[NROI];
__device__ float g_w[NROI];
__device__ int   g_list[NROI];
__device__ int   g_cnt;

// ============================================================
// Kernel 0: coalesced transpose of preds = pc[:,1:]*pd[:,1:]
// ============================================================
__global__ void preds_kernel(const float* __restrict__ pc,
                             const float* __restrict__ pd) {
    __shared__ float sp[128 * 21];
    const int i0 = blockIdx.x * 128;
    for (int idx = threadIdx.x; idx < 128 * 21; idx += blockDim.x)
        sp[idx] = pc[i0 * 21 + idx] * pd[i0 * 21 + idx];
    __syncthreads();
    #pragma unroll
    for (int c = 0; c < NCLS; ++c)
        for (int i = threadIdx.x; i < 128; i += blockDim.x)
            g_predsT[c * NROI + i0 + i] = sp[i * 21 + c + 1];
}

// ============================================================
// Kernel 1: one block per class (20 blocks, 1024 threads)
// ============================================================
__global__ void __launch_bounds__(1024, 1)
class_nms_kernel(const float* __restrict__ iou) {
    __shared__ unsigned int skey[NROI];                 // 24KB
    __shared__ unsigned long long cand[CSORT];          // 8KB
    __shared__ unsigned int sh_hist[256];
    __shared__ unsigned int sh_wsum[8];
    __shared__ unsigned int sh_prefix, sh_k;
    __shared__ int sh_nc, sh_next;
    __shared__ unsigned int am[AW];

    const int c   = blockIdx.x;
    const int tid = threadIdx.x;
    const int nt  = blockDim.x;

    if (c == 0 && tid == 0) g_cnt = 0;

    for (int i = tid; i < NROI; i += nt) g_keep[c * NROI + i] = 0;
    for (int i = tid; i < NROI; i += nt)
        skey[i] = ~__float_as_uint(g_predsT[c * NROI + i]);

    if (tid == 0) { sh_prefix = 0; sh_k = KSEL; }
    __syncthreads();

    // ---- 4-pass MSB radix select with parallel bin scan ----
    for (int shift = 24; shift >= 0; shift -= 8) {
        if (tid < 256) sh_hist[tid] = 0;
        __syncthreads();
        const unsigned int prefix = sh_prefix;
        const unsigned int kcur   = sh_k;
        const unsigned int pmask  = (shift == 24) ? 0u : (0xFFFFFFFFu << (shift + 8));
        for (int i = tid; i < NROI; i += nt) {
            unsigned int key = skey[i];
            if ((key & pmask) == prefix)
                atomicAdd(&sh_hist[(key >> shift) & 0xFF], 1u);
        }
        __syncthreads();
        // two-level inclusive scan of 256 bins (warps 0..7)
        unsigned int x = 0, hval = 0;
        if (tid < 256) {
            hval = sh_hist[tid];
            x = hval;
            #pragma unroll
            for (int off = 1; off < 32; off <<= 1) {
                unsigned int y = __shfl_up_sync(0xFFFFFFFFu, x, off);
                if ((tid & 31) >= off) x += y;
            }
            if ((tid & 31) == 31) sh_wsum[tid >> 5] = x;
        }
        __syncthreads();
        if (tid < 8) {
            unsigned int w = sh_wsum[tid];
            #pragma unroll
            for (int off = 1; off < 8; off <<= 1) {
                unsigned int y = __shfl_up_sync(0xFFu, w, off);
                if (tid >= off) w += y;
            }
            sh_wsum[tid] = w;
        }
        __syncthreads();
        if (tid < 256) {
            unsigned int incl = x + ((tid >= 32) ? sh_wsum[(tid >> 5) - 1] : 0u);
            unsigned int excl = incl - hval;
            if (incl >= kcur && excl < kcur) {
                sh_prefix = prefix | ((unsigned int)tid << shift);
                sh_k = kcur - excl;
            }
        }
        __syncthreads();
    }
    const unsigned int thr = sh_prefix;

    // ---- compact candidates (key <= thr) ----
    if (tid == 0) sh_nc = 0;
    __syncthreads();
    for (int i = tid; i < NROI; i += nt) {
        unsigned int key = skey[i];
        if (key <= thr) {
            int pos = atomicAdd(&sh_nc, 1);
            if (pos < CSORT)
                cand[pos] = ((unsigned long long)key << 32) | (unsigned int)i;
        }
    }
    __syncthreads();
    const int nc = sh_nc;
    if (tid >= nc && tid < CSORT) cand[tid] = 0xFFFFFFFFFFFFFFFFull;
    __syncthreads();

    // ---- bitonic sort 1024 u64: shfl for j<=16, smem for j>=32 ----
    {
        unsigned long long v = cand[tid];
        #pragma unroll
        for (unsigned int k = 2; k <= 32; k <<= 1) {
            bool asc = ((tid & k) == 0);
            #pragma unroll
            for (unsigned int j = k >> 1; j >= 1; j >>= 1) {
                unsigned long long o = __shfl_xor_sync(0xFFFFFFFFu, v, j);
                bool keepmin = (((tid & j) == 0) == asc);
                v = (keepmin == (v <= o)) ? v : o;
            }
        }
        cand[tid] = v;
    }
    __syncthreads();
    for (unsigned int k = 64; k <= CSORT; k <<= 1) {
        for (unsigned int j = k >> 1; j >= 32; j >>= 1) {
            unsigned int i = tid, ixj = i ^ j;
            if (ixj > i) {
                unsigned long long a = cand[i], b = cand[ixj];
                bool asc = ((i & k) == 0);
                if ((a > b) == asc) { cand[i] = b; cand[ixj] = a; }
            }
            __syncthreads();
        }
        {
            unsigned long long v = cand[tid];
            bool asc = ((tid & k) == 0);
            #pragma unroll
            for (unsigned int j = 16; j >= 1; j >>= 1) {
                unsigned long long o = __shfl_xor_sync(0xFFFFFFFFu, v, j);
                bool keepmin = (((tid & j) == 0) == asc);
                v = (keepmin == (v <= o)) ? v : o;
            }
            cand[tid] = v;
        }
        __syncthreads();
    }

    // ---- greedy NMS with alive bitmask + skip scan ----
    for (int w = tid; w < AW; w += nt) am[w] = 0xFFFFFFFFu;
    if (tid == 0) {
        am[AW - 1] = (1u << (KSEL - 32 * (AW - 1))) - 1;
        sh_next = 0;
    }
    __syncthreads();

    while (true) {
        const int i = sh_next;
        if (i >= KSEL) break;
        const int oi = (unsigned int)cand[i];
        if (tid == 0) g_keep[c * NROI + oi] = 1;
        const int j = i + 1 + tid;
        if (j < KSEL) {
            const int oj = (unsigned int)cand[j];
            float v = iou[(size_t)oi * NROI + oj];
            if (v >= IOU_TH) atomicAnd(&am[j >> 5], ~(1u << (j & 31)));
        }
        __syncthreads();
        if (tid == 0) {
            int nx = KSEL;
            int start = i + 1;
            int w = start >> 5;
            unsigned int m = (w < AW) ? (am[w] & (0xFFFFFFFFu << (start & 31))) : 0u;
            while (true) {
                if (m) { nx = (w << 5) + __ffs(m) - 1; break; }
                if (++w >= AW) break;
                m = am[w];
            }
            sh_next = nx;
        }
        __syncthreads();
    }
}

// ============================================================
// Kernel 2: per-ROI class resolution + gt compaction
// ============================================================
__global__ void combine_kernel(const int* __restrict__ labels) {
    int i = blockIdx.x * blockDim.x + threadIdx.x;
    if (i >= NROI) return;
    float w = -1.0f;
    int cls = 0;
    #pragma unroll
    for (int c = 0; c < NCLS; ++c) {
        if (labels[c] > 0 && g_keep[c * NROI + i]) {
            float p = g_predsT[c * NROI + i];
            if (p > w) { w = p; cls = c + 1; }
        }
    }
    g_cls[i] = cls;
    g_w[i]   = w;
    if (cls > 0) {
        int pos = atomicAdd(&g_cnt, 1);
        g_list[pos] = i;
    }
}

// ============================================================
// Kernel 3: masked max/argmax over gt columns, 4-way ILP.
// Tie-break (smallest j) is order-independent => parallel accs OK.
// ============================================================
__device__ __forceinline__ void upd(float& mv, int& mj, float v, int j) {
    if (v > mv || (v == mv && j < mj)) { mv = v; mj = j; }
}

__global__ void __launch_bounds__(FB)
final_kernel(const float* __restrict__ iou, float* __restrict__ out) {
    __shared__ int sj[256];
    const int i = blockIdx.x * FB + threadIdx.x;
    const int G = g_cnt;

    float mv0 = -1.0f, mv1 = -1.0f, mv2 = -1.0f, mv3 = -1.0f;
    int   mj0 = 0,     mj1 = 0,     mj2 = 0,     mj3 = 0;

    for (int base = 0; base < G; base += 256) {
        const int tile = min(256, G - base);
        for (int t = threadIdx.x; t < tile; t += FB) sj[t] = g_list[base + t];
        __syncthreads();
        int t = 0;
        for (; t + 4 <= tile; t += 4) {
            int j0 = sj[t], j1 = sj[t + 1], j2 = sj[t + 2], j3 = sj[t + 3];
            float v0 = iou[(size_t)j0 * NROI + i];
            float v1 = iou[(size_t)j1 * NROI + i];
            float v2 = iou[(size_t)j2 * NROI + i];
            float v3 = iou[(size_t)j3 * NROI + i];
            upd(mv0, mj0, v0, j0); upd(mv1, mj1, v1, j1);
            upd(mv2, mj2, v2, j2); upd(mv3, mj3, v3, j3);
        }
        for (; t < tile; ++t) {
            int j0 = sj[t];
            upd(mv0, mj0, iou[(size_t)j0 * NROI + i], j0);
        }
        __syncthreads();
    }
    upd(mv0, mj0, mv1, mj1);
    upd(mv2, mj2, mv3, mj3);
    upd(mv0, mj0, mv2, mj2);

    const int   cls = g_cls[mj0];
    const float lw  = g_w[mj0];
    const bool ignore = (mv0 == 0.0f);
    const bool bg     = (mv0 < IOU_TH) && !ignore;
    const int lab = ignore ? -1 : (bg ? 0 : cls);
    #pragma unroll
    for (int k = 0; k <= NCLS; ++k)
        out[(size_t)i * (NCLS + 1) + k] = (k == lab) ? 1.0f : 0.0f;
    out[(size_t)NROI * (NCLS + 1) + i]        = mv0;
    out[(size_t)NROI * (NCLS + 1) + NROI + i] = ignore ? 0.0f : lw;
}

extern "C" void kernel_launch(void* const* d_in, const int* in_sizes, int n_in,
                              void* d_out, int out_size) {
    const float* pc     = (const float*)d_in[0];
    const float* pd     = (const float*)d_in[1];
    const int*   labels = (const int*)d_in[3];
    const float* iou    = (const float*)d_in[4];
    float* out = (float*)d_out;

    preds_kernel<<<NROI / 128, 128>>>(pc, pd);
    class_nms_kernel<<<NCLS, 1024>>>(iou);
    combine_kernel<<<(NROI + 255) / 256, 256>>>(labels);
    final_kernel<<<NROI / FB, FB>>>(iou, out);
}

// round 4
// speedup vs baseline: 4.1240x; 1.0498x over previous
#include <cuda_runtime.h>
#include <cstdint>

#define NROI 6144
#define NCLS 20
#define KSEL 615            // ceil(0.1 * 6144)
#define CSORT 1024
#define AW 20               // ceil(KSEL/32)
#define IOU_TH 0.25f
#define GCH 8               // g-chunks in partial kernel

// ---- scratch (device globals; no allocations allowed) ----
__device__ unsigned long long g_cw[NROI];    // packed (prob_bits<<32)|(NCLS-c); 0 = no label
__device__ unsigned long long g_best[NROI];  // packed (v_bits<<32)|(NROI-j)
__device__ int g_list[NROI];
__device__ int g_cnt;

// ============================================================
// Kernel 0: reset per-launch state (graph replays reuse globals)
// ============================================================
__global__ void init_kernel() {
    int i = blockIdx.x * blockDim.x + threadIdx.x;
    if (i < NROI) g_cw[i] = 0ull;
    if (i == 0) g_cnt = 0;
}

// ============================================================
// Kernel 1: one block per class. Skips label==0 classes entirely
// (reference gates all updates on labels[c]>0).
// radix-select -> compact -> hybrid bitonic sort -> greedy NMS
// -> publish (prob, class) via atomicMax (exact sequential semantics:
//    strictly-greater prob wins; equal prob -> smaller c wins).
// ============================================================
__global__ void __launch_bounds__(1024, 1)
class_nms_kernel(const float* __restrict__ pc,
                 const float* __restrict__ pd,
                 const int* __restrict__ labels,
                 const float* __restrict__ iou) {
    __shared__ unsigned int skey[NROI];                 // 24KB
    __shared__ unsigned long long cand[CSORT];          // 8KB
    __shared__ unsigned int sh_hist[256];
    __shared__ unsigned int sh_wsum[8];
    __shared__ unsigned int sh_prefix, sh_k;
    __shared__ int sh_nc, sh_next;
    __shared__ unsigned int am[AW];

    const int c   = blockIdx.x;
    const int tid = threadIdx.x;
    const int nt  = blockDim.x;

    if (labels[c] == 0) return;                         // class contributes nothing

    // build inverted float keys directly from pc/pd (strided, latency-hidden)
    for (int i = tid; i < NROI; i += nt) {
        float p = __ldg(&pc[i * (NCLS + 1) + c + 1]) * __ldg(&pd[i * (NCLS + 1) + c + 1]);
        skey[i] = ~__float_as_uint(p);
    }
    if (tid == 0) { sh_prefix = 0; sh_k = KSEL; }
    __syncthreads();

    // ---- 4-pass MSB radix select with parallel bin scan ----
    for (int shift = 24; shift >= 0; shift -= 8) {
        if (tid < 256) sh_hist[tid] = 0;
        __syncthreads();
        const unsigned int prefix = sh_prefix;
        const unsigned int kcur   = sh_k;
        const unsigned int pmask  = (shift == 24) ? 0u : (0xFFFFFFFFu << (shift + 8));
        for (int i = tid; i < NROI; i += nt) {
            unsigned int key = skey[i];
            if ((key & pmask) == prefix)
                atomicAdd(&sh_hist[(key >> shift) & 0xFF], 1u);
        }
        __syncthreads();
        unsigned int x = 0, hval = 0;
        if (tid < 256) {
            hval = sh_hist[tid];
            x = hval;
            #pragma unroll
            for (int off = 1; off < 32; off <<= 1) {
                unsigned int y = __shfl_up_sync(0xFFFFFFFFu, x, off);
                if ((tid & 31) >= off) x += y;
            }
            if ((tid & 31) == 31) sh_wsum[tid >> 5] = x;
        }
        __syncthreads();
        if (tid < 8) {
            unsigned int w = sh_wsum[tid];
            #pragma unroll
            for (int off = 1; off < 8; off <<= 1) {
                unsigned int y = __shfl_up_sync(0xFFu, w, off);
                if (tid >= off) w += y;
            }
            sh_wsum[tid] = w;
        }
        __syncthreads();
        if (tid < 256) {
            unsigned int incl = x + ((tid >= 32) ? sh_wsum[(tid >> 5) - 1] : 0u);
            unsigned int excl = incl - hval;
            if (incl >= kcur && excl < kcur) {
                sh_prefix = prefix | ((unsigned int)tid << shift);
                sh_k = kcur - excl;
            }
        }
        __syncthreads();
    }
    const unsigned int thr = sh_prefix;

    // ---- compact candidates (key <= thr) ----
    if (tid == 0) sh_nc = 0;
    __syncthreads();
    for (int i = tid; i < NROI; i += nt) {
        unsigned int key = skey[i];
        if (key <= thr) {
            int pos = atomicAdd(&sh_nc, 1);
            if (pos < CSORT)
                cand[pos] = ((unsigned long long)key << 32) | (unsigned int)i;
        }
    }
    __syncthreads();
    const int nc = sh_nc;
    if (tid >= nc && tid < CSORT) cand[tid] = 0xFFFFFFFFFFFFFFFFull;
    __syncthreads();

    // ---- bitonic sort 1024 u64: shfl for j<=16, smem for j>=32 ----
    {
        unsigned long long v = cand[tid];
        #pragma unroll
        for (unsigned int k = 2; k <= 32; k <<= 1) {
            bool asc = ((tid & k) == 0);
            #pragma unroll
            for (unsigned int j = k >> 1; j >= 1; j >>= 1) {
                unsigned long long o = __shfl_xor_sync(0xFFFFFFFFu, v, j);
                bool keepmin = (((tid & j) == 0) == asc);
                v = (keepmin == (v <= o)) ? v : o;
            }
        }
        cand[tid] = v;
    }
    __syncthreads();
    for (unsigned int k = 64; k <= CSORT; k <<= 1) {
        for (unsigned int j = k >> 1; j >= 32; j >>= 1) {
            unsigned int i = tid, ixj = i ^ j;
            if (ixj > i) {
                unsigned long long a = cand[i], b = cand[ixj];
                bool asc = ((i & k) == 0);
                if ((a > b) == asc) { cand[i] = b; cand[ixj] = a; }
            }
            __syncthreads();
        }
        {
            unsigned long long v = cand[tid];
            bool asc = ((tid & k) == 0);
            #pragma unroll
            for (unsigned int j = 16; j >= 1; j >>= 1) {
                unsigned long long o = __shfl_xor_sync(0xFFFFFFFFu, v, j);
                bool keepmin = (((tid & j) == 0) == asc);
                v = (keepmin == (v <= o)) ? v : o;
            }
            cand[tid] = v;
        }
        __syncthreads();
    }

    // ---- greedy NMS with alive bitmask + skip scan; publish kept ----
    for (int w = tid; w < AW; w += nt) am[w] = 0xFFFFFFFFu;
    if (tid == 0) {
        am[AW - 1] = (1u << (KSEL - 32 * (AW - 1))) - 1;
        sh_next = 0;
    }
    __syncthreads();

    while (true) {
        const int i = sh_next;
        if (i >= KSEL) break;
        const unsigned long long ci = cand[i];
        const int oi = (unsigned int)ci;
        if (tid == 0) {
            unsigned int pbits = ~(unsigned int)(ci >> 32);
            atomicMax(&g_cw[oi],
                      ((unsigned long long)pbits << 32) |
                      (unsigned long long)(unsigned int)(NCLS - c));
        }
        const int j = i + 1 + tid;
        if (j < KSEL) {
            const int oj = (unsigned int)cand[j];
            float v = iou[(size_t)oi * NROI + oj];
            if (v >= IOU_TH) atomicAnd(&am[j >> 5], ~(1u << (j & 31)));
        }
        __syncthreads();
        if (tid == 0) {
            int nx = KSEL;
            int start = i + 1;
            int w = start >> 5;
            unsigned int m = (w < AW) ? (am[w] & (0xFFFFFFFFu << (start & 31))) : 0u;
            while (true) {
                if (m) { nx = (w << 5) + __ffs(m) - 1; break; }
                if (++w >= AW) break;
                m = am[w];
            }
            sh_next = nx;
        }
        __syncthreads();
    }
}

// ============================================================
// Kernel 2: compact gt indices + zero g_best
// ============================================================
__global__ void gtlist_kernel() {
    int i = blockIdx.x * blockDim.x + threadIdx.x;
    if (i >= NROI) return;
    g_best[i] = 0ull;
    if (g_cw[i] != 0ull) {
        int pos = atomicAdd(&g_cnt, 1);
        g_list[pos] = i;
    }
}

// ============================================================
// Kernel 3: partial masked max over a g-chunk, merged by
// packed-u64 atomicMax (exact smallest-j tie-break).
// ============================================================
__device__ __forceinline__ void upd(float& mv, int& mj, float v, int j) {
    if (v > mv || (v == mv && j < mj)) { mv = v; mj = j; }
}

__global__ void __launch_bounds__(128)
partial_kernel(const float* __restrict__ iou) {
    const int i = blockIdx.x * 128 + threadIdx.x;
    const int G = g_cnt;
    const int len = (G + GCH - 1) / GCH;
    const int g0 = blockIdx.y * len;
    const int g1 = min(G, g0 + len);
    if (g0 >= g1) return;

    float mv0 = -1.0f, mv1 = -1.0f, mv2 = -1.0f, mv3 = -1.0f;
    int   mj0 = 0,     mj1 = 0,     mj2 = 0,     mj3 = 0;
    int g = g0;
    for (; g + 4 <= g1; g += 4) {
        int j0 = __ldg(&g_list[g]),     j1 = __ldg(&g_list[g + 1]);
        int j2 = __ldg(&g_list[g + 2]), j3 = __ldg(&g_list[g + 3]);
        float v0 = iou[(size_t)j0 * NROI + i];
        float v1 = iou[(size_t)j1 * NROI + i];
        float v2 = iou[(size_t)j2 * NROI + i];
        float v3 = iou[(size_t)j3 * NROI + i];
        upd(mv0, mj0, v0, j0); upd(mv1, mj1, v1, j1);
        upd(mv2, mj2, v2, j2); upd(mv3, mj3, v3, j3);
    }
    for (; g < g1; ++g) {
        int j0 = __ldg(&g_list[g]);
        upd(mv0, mj0, iou[(size_t)j0 * NROI + i], j0);
    }
    upd(mv0, mj0, mv1, mj1);
    upd(mv2, mj2, mv3, mj3);
    upd(mv0, mj0, mv2, mj2);

    unsigned long long key =
        ((unsigned long long)__float_as_uint(mv0) << 32) |
        (unsigned long long)(unsigned int)(NROI - mj0);
    atomicMax(&g_best[i], key);
}

// ============================================================
// Kernel 4: unpack + emit outputs
// ============================================================
__global__ void __launch_bounds__(128)
final_out_kernel(float* __restrict__ out) {
    const int i = blockIdx.x * 128 + threadIdx.x;
    unsigned long long b = g_best[i];
    float maxv = __uint_as_float((unsigned int)(b >> 32));
    int   maxj = NROI - (int)(unsigned int)(b & 0xFFFFFFFFull);

    unsigned long long cw = g_cw[maxj];
    int   cls = (int)(NCLS + 1) - (int)(unsigned int)(cw & 0xFFFFFFFFull);  // = c+1
    float lw  = __uint_as_float((unsigned int)(cw >> 32));

    const bool ignore = (maxv == 0.0f);
    const bool bg     = (maxv < IOU_TH) && !ignore;
    const int  lab    = ignore ? -1 : (bg ? 0 : cls);

    #pragma unroll
    for (int k = 0; k <= NCLS; ++k)
        out[(size_t)i * (NCLS + 1) + k] = (k == lab) ? 1.0f : 0.0f;
    out[(size_t)NROI * (NCLS + 1) + i]        = maxv;
    out[(size_t)NROI * (NCLS + 1) + NROI + i] = ignore ? 0.0f : lw;
}

extern "C" void kernel_launch(void* const* d_in, const int* in_sizes, int n_in,
                              void* d_out, int out_size) {
    const float* pc     = (const float*)d_in[0];
    const float* pd     = (const float*)d_in[1];
    // d_in[2] = rois (unused)
    const int*   labels = (const int*)d_in[3];
    const float* iou    = (const float*)d_in[4];
    float* out = (float*)d_out;

    init_kernel<<<6, 1024>>>();
    class_nms_kernel<<<NCLS, 1024>>>(pc, pd, labels, iou);
    gtlist_kernel<<<6, 1024>>>();
    partial_kernel<<<dim3(NROI / 128, GCH), 128>>>(iou);
    final_out_kernel<<<NROI / 128, 128>>>(out);
}